// round 1
// baseline (speedup 1.0000x reference)
#include <cuda_runtime.h>
#include <cstdint>

#define BATCH 2
#define SEQ   2048
#define DMODEL 1024
#define NHEAD 16
#define HDIM  64
#define HWIN  64          // band half-width (W//2)
#define MROWS (BATCH*SEQ) // 4096

// ---------------- scratch (no runtime allocation allowed) ----------------
__device__ float g_q[(size_t)MROWS * DMODEL];
__device__ float g_k[(size_t)MROWS * DMODEL];
__device__ float g_v[(size_t)MROWS * DMODEL];
__device__ float g_ctx[(size_t)MROWS * DMODEL];

// ---------------- GEMM: C[M,N] = A[M,K] @ B[N,K]^T + bias[N] --------------
// 128x128 block, BK=8, 256 threads, 8x8 microtile, float4 paths.
__global__ __launch_bounds__(256) void gemm_nt_bias(
    const float* __restrict__ A, const float* __restrict__ B,
    const float* __restrict__ bias, float* __restrict__ C,
    int M, int N, int K)
{
    __shared__ float As[8][132];
    __shared__ float Bs[8][132];

    const int tid = threadIdx.x;
    const int bm = blockIdx.y * 128;
    const int bn = blockIdx.x * 128;
    const int lr = tid >> 1;          // 0..127
    const int lc = (tid & 1) << 2;    // 0 or 4

    const float* Aptr = A + (size_t)(bm + lr) * K + lc;
    const float* Bptr = B + (size_t)(bn + lr) * K + lc;

    const int tx = tid & 15, ty = tid >> 4;

    float acc[8][8];
#pragma unroll
    for (int i = 0; i < 8; i++)
#pragma unroll
        for (int j = 0; j < 8; j++) acc[i][j] = 0.f;

    for (int kt = 0; kt < K; kt += 8) {
        float4 av = *(const float4*)(Aptr + kt);
        float4 bv = *(const float4*)(Bptr + kt);
        __syncthreads();
        As[lc + 0][lr] = av.x; As[lc + 1][lr] = av.y;
        As[lc + 2][lr] = av.z; As[lc + 3][lr] = av.w;
        Bs[lc + 0][lr] = bv.x; Bs[lc + 1][lr] = bv.y;
        Bs[lc + 2][lr] = bv.z; Bs[lc + 3][lr] = bv.w;
        __syncthreads();
#pragma unroll
        for (int kk = 0; kk < 8; kk++) {
            float4 a0 = *(const float4*)&As[kk][ty * 4];
            float4 a1 = *(const float4*)&As[kk][64 + ty * 4];
            float4 b0 = *(const float4*)&Bs[kk][tx * 4];
            float4 b1 = *(const float4*)&Bs[kk][64 + tx * 4];
            float ar[8] = {a0.x, a0.y, a0.z, a0.w, a1.x, a1.y, a1.z, a1.w};
            float br[8] = {b0.x, b0.y, b0.z, b0.w, b1.x, b1.y, b1.z, b1.w};
#pragma unroll
            for (int i = 0; i < 8; i++)
#pragma unroll
                for (int j = 0; j < 8; j++)
                    acc[i][j] += ar[i] * br[j];
        }
    }

    const int n0 = bn + tx * 4;
    const int n1 = bn + 64 + tx * 4;
    float4 bias0 = *(const float4*)&bias[n0];
    float4 bias1 = *(const float4*)&bias[n1];
#pragma unroll
    for (int i = 0; i < 8; i++) {
        int m = bm + ((i < 4) ? (ty * 4 + i) : (64 + ty * 4 + i - 4));
        float4 r0, r1;
        r0.x = acc[i][0] + bias0.x; r0.y = acc[i][1] + bias0.y;
        r0.z = acc[i][2] + bias0.z; r0.w = acc[i][3] + bias0.w;
        r1.x = acc[i][4] + bias1.x; r1.y = acc[i][5] + bias1.y;
        r1.z = acc[i][6] + bias1.z; r1.w = acc[i][7] + bias1.w;
        *(float4*)&C[(size_t)m * N + n0] = r0;
        *(float4*)&C[(size_t)m * N + n1] = r1;
    }
}

// ---------------- banded attention ---------------------------------------
// 8 warps per block = 8 consecutive queries of one (b,h).
// Phase 1: K tile in shared -> scores -> softmax -> write attn band + ps.
// Phase 2: reuse tile for V -> ctx.
#define QB 8
#define KSPAN (QB - 1 + 2 * HWIN + 1)   // 136
#define KST 65

__global__ __launch_bounds__(256) void local_attn_kernel(
    const float* __restrict__ Qg, const float* __restrict__ Kg,
    const float* __restrict__ Vg, float* __restrict__ attn,
    float* __restrict__ ctx)
{
    __shared__ float tile[KSPAN][KST];
    __shared__ float qs[QB][HDIM];
    __shared__ float ps[QB][136];

    const int b = blockIdx.z, h = blockIdx.y;
    const int q0 = blockIdx.x * QB;
    const int tid = threadIdx.x;
    const int warp = tid >> 5, lane = tid & 31;

    const int tbase = q0 - HWIN;                   // may be negative
    const int glo = tbase < 0 ? 0 : tbase;
    int ghi = q0 + QB - 1 + HWIN; if (ghi > SEQ - 1) ghi = SEQ - 1;
    const int nrows = ghi - glo + 1;
    const int sh0 = glo - tbase;                   // shared row of glo

    // load q rows for this block
    for (int idx = tid; idx < QB * HDIM; idx += 256) {
        int qi = idx >> 6, d = idx & 63;
        qs[qi][d] = Qg[((size_t)(b * SEQ + q0 + qi)) * DMODEL + h * HDIM + d];
    }
    // load K tile
    for (int idx = tid; idx < nrows * HDIM; idx += 256) {
        int r = idx >> 6, d = idx & 63;
        tile[sh0 + r][d] = Kg[((size_t)(b * SEQ + glo + r)) * DMODEL + h * HDIM + d];
    }
    __syncthreads();

    const int i = q0 + warp;
    int lo = i - HWIN; if (lo < 0) lo = 0;
    int hi = i + HWIN; if (hi > SEQ - 1) hi = SEQ - 1;
    const int nk = hi - lo + 1;                    // 65..129
    const int soff = lo - tbase;

    int roff[5]; bool valid[5];
#pragma unroll
    for (int c = 0; c < 5; c++) {
        int jj = lane + 32 * c;
        valid[c] = (jj < nk);
        int jc = valid[c] ? jj : (nk - 1);
        roff[c] = (soff + jc) * KST;
    }

    const float* tf = &tile[0][0];
    const float* qw = qs[warp];
    float s0 = 0.f, s1 = 0.f, s2 = 0.f, s3 = 0.f, s4 = 0.f;
#pragma unroll 16
    for (int d = 0; d < HDIM; d++) {
        float qd = qw[d];
        s0 += qd * tf[roff[0] + d];
        s1 += qd * tf[roff[1] + d];
        s2 += qd * tf[roff[2] + d];
        s3 += qd * tf[roff[3] + d];
        s4 += qd * tf[roff[4] + d];
    }

    float sc[5] = {s0, s1, s2, s3, s4};
    float mx = -1e30f;
#pragma unroll
    for (int c = 0; c < 5; c++) {
        sc[c] = valid[c] ? sc[c] * 0.125f : -1e30f;
        mx = fmaxf(mx, sc[c]);
    }
#pragma unroll
    for (int o = 16; o; o >>= 1) mx = fmaxf(mx, __shfl_xor_sync(0xffffffffu, mx, o));
    float sum = 0.f;
#pragma unroll
    for (int c = 0; c < 5; c++) {
        sc[c] = valid[c] ? __expf(sc[c] - mx) : 0.f;
        sum += sc[c];
    }
#pragma unroll
    for (int o = 16; o; o >>= 1) sum += __shfl_xor_sync(0xffffffffu, sum, o);
    const float inv = 1.f / sum;

    const size_t arow = ((((size_t)b * NHEAD + h) * SEQ) + i) * SEQ + lo;
#pragma unroll
    for (int c = 0; c < 5; c++) {
        int jj = lane + 32 * c;
        if (jj < nk) {
            float p = sc[c] * inv;
            attn[arow + jj] = p;
            ps[warp][jj] = p;
        }
    }
    __syncthreads();

    // load V into the same tile
    for (int idx = tid; idx < nrows * HDIM; idx += 256) {
        int r = idx >> 6, d = idx & 63;
        tile[sh0 + r][d] = Vg[((size_t)(b * SEQ + glo + r)) * DMODEL + h * HDIM + d];
    }
    __syncthreads();

    float a0 = 0.f, a1 = 0.f;
    const int d0 = lane, d1 = lane + 32;
    const float* pw = ps[warp];
    for (int j = 0; j < nk; j++) {
        float p = pw[j];
        a0 += p * tile[soff + j][d0];
        a1 += p * tile[soff + j][d1];
    }
    const size_t cbase = ((size_t)(b * SEQ + i)) * DMODEL + h * HDIM;
    ctx[cbase + d0] = a0;
    ctx[cbase + d1] = a1;
}

// ---------------- launch ---------------------------------------------------
extern "C" void kernel_launch(void* const* d_in, const int* in_sizes, int n_in,
                              void* d_out, int out_size)
{
    const float* x  = (const float*)d_in[0];
    const float* Wq = (const float*)d_in[1];
    const float* bq = (const float*)d_in[2];
    const float* Wk = (const float*)d_in[3];
    const float* bk = (const float*)d_in[4];
    const float* Wv = (const float*)d_in[5];
    const float* bv = (const float*)d_in[6];
    const float* Wo = (const float*)d_in[7];
    const float* bo = (const float*)d_in[8];

    float* out  = (float*)d_out;                               // [B,S,D]
    float* attn = out + (size_t)MROWS * DMODEL;                // [B,H,S,S]

    float *pq, *pk, *pv, *pc;
    cudaGetSymbolAddress((void**)&pq, g_q);
    cudaGetSymbolAddress((void**)&pk, g_k);
    cudaGetSymbolAddress((void**)&pv, g_v);
    cudaGetSymbolAddress((void**)&pc, g_ctx);

    // zero-fill dense attn output (band entries overwritten below)
    cudaMemsetAsync(attn, 0,
                    (size_t)BATCH * NHEAD * SEQ * SEQ * sizeof(float), 0);

    dim3 gblk(DMODEL / 128, MROWS / 128);   // (8, 32)
    gemm_nt_bias<<<gblk, 256>>>(x, Wq, bq, pq, MROWS, DMODEL, DMODEL);
    gemm_nt_bias<<<gblk, 256>>>(x, Wk, bk, pk, MROWS, DMODEL, DMODEL);
    gemm_nt_bias<<<gblk, 256>>>(x, Wv, bv, pv, MROWS, DMODEL, DMODEL);

    dim3 gattn(SEQ / QB, NHEAD, BATCH);     // (256, 16, 2)
    local_attn_kernel<<<gattn, 256>>>(pq, pk, pv, attn, pc);

    gemm_nt_bias<<<gblk, 256>>>(pc, Wo, bo, out, MROWS, DMODEL, DMODEL);
}

// round 4
// speedup vs baseline: 1.4580x; 1.4580x over previous
#include <cuda_runtime.h>
#include <cuda_bf16.h>
#include <cstdint>

#define BATCH 2
#define SEQ   2048
#define DMODEL 1024
#define NHEAD 16
#define HDIM  64
#define HWIN  64
#define MROWS (BATCH*SEQ)

// ---------------- scratch ----------------
__device__ float g_q[(size_t)MROWS * DMODEL];
__device__ float g_k[(size_t)MROWS * DMODEL];
__device__ float g_v[(size_t)MROWS * DMODEL];
__device__ float g_ctx[(size_t)MROWS * DMODEL];
// bf16 hi/lo splits
__device__ __nv_bfloat16 g_xh[(size_t)MROWS * DMODEL];
__device__ __nv_bfloat16 g_xl[(size_t)MROWS * DMODEL];
__device__ __nv_bfloat16 g_ch[(size_t)MROWS * DMODEL];
__device__ __nv_bfloat16 g_cl[(size_t)MROWS * DMODEL];
__device__ __nv_bfloat16 g_wh[4][(size_t)DMODEL * DMODEL];
__device__ __nv_bfloat16 g_wl[4][(size_t)DMODEL * DMODEL];

// ---------------- helpers ----------------
__device__ __forceinline__ uint32_t smem_u32(const void* p) {
    uint32_t a;
    asm("{ .reg .u64 t; cvta.to.shared.u64 t, %1; cvt.u32.u64 %0, t; }" : "=r"(a) : "l"(p));
    return a;
}
__device__ __forceinline__ void cp16(uint32_t s, const void* g) {
    asm volatile("cp.async.cg.shared.global [%0], [%1], 16;" :: "r"(s), "l"(g));
}
#define CP_COMMIT() asm volatile("cp.async.commit_group;" ::: "memory")
#define CP_WAIT1()  asm volatile("cp.async.wait_group 1;" ::: "memory")

#define LDSM_X4(r0,r1,r2,r3,addr) \
    asm volatile("ldmatrix.sync.aligned.m8n8.x4.shared.b16 {%0,%1,%2,%3}, [%4];" \
                 : "=r"(r0), "=r"(r1), "=r"(r2), "=r"(r3) : "r"(addr))

#define MMA16816(d, a0,a1,a2,a3, b0,b1) \
    asm volatile("mma.sync.aligned.m16n8k16.row.col.f32.bf16.bf16.f32 " \
                 "{%0,%1,%2,%3}, {%4,%5,%6,%7}, {%8,%9}, {%0,%1,%2,%3};" \
                 : "+f"((d)[0]), "+f"((d)[1]), "+f"((d)[2]), "+f"((d)[3]) \
                 : "r"(a0), "r"(a1), "r"(a2), "r"(a3), "r"(b0), "r"(b1))

// ---------------- split fp32 -> bf16 hi + bf16 residual --------------------
__global__ __launch_bounds__(256) void split_bf16(
    const float* __restrict__ src, __nv_bfloat16* __restrict__ hi,
    __nv_bfloat16* __restrict__ lo, int n4)
{
    int idx = blockIdx.x * 256 + threadIdx.x;
    int stride = gridDim.x * 256;
    for (; idx < n4; idx += stride) {
        float4 v = ((const float4*)src)[idx];
        __nv_bfloat16 hx = __float2bfloat16(v.x), hy = __float2bfloat16(v.y);
        __nv_bfloat16 hz = __float2bfloat16(v.z), hw = __float2bfloat16(v.w);
        float lx = v.x - __bfloat162float(hx), ly = v.y - __bfloat162float(hy);
        float lz = v.z - __bfloat162float(hz), lw = v.w - __bfloat162float(hw);
        uint2 hp, lp;
        hp.x = ((uint32_t)__bfloat16_as_ushort(hy) << 16) | __bfloat16_as_ushort(hx);
        hp.y = ((uint32_t)__bfloat16_as_ushort(hw) << 16) | __bfloat16_as_ushort(hz);
        lp.x = ((uint32_t)__bfloat16_as_ushort(__float2bfloat16(ly)) << 16) |
               __bfloat16_as_ushort(__float2bfloat16(lx));
        lp.y = ((uint32_t)__bfloat16_as_ushort(__float2bfloat16(lw)) << 16) |
               __bfloat16_as_ushort(__float2bfloat16(lz));
        ((uint2*)hi)[idx] = hp;
        ((uint2*)lo)[idx] = lp;
    }
}

// ---------------- tensor GEMM via mma.sync --------------------------------
// C[M=4096,1024] = Ah.Bh^T + Ah.Bl^T + Al.Bh^T + bias  (96 K-chunks of 32)
#define ROWB   80                    // padded row stride bytes (64B payload)
#define ASTAGE (128 * ROWB)          // 10240
#define STAGE  (2 * ASTAGE)          // 20480
#define NSTG   3
#define GEMM_SMEM (NSTG * STAGE)     // 61440
#define NCHUNK 96

__global__ __launch_bounds__(256) void gemm_tc(
    const __nv_bfloat16* __restrict__ Ah, const __nv_bfloat16* __restrict__ Al,
    const __nv_bfloat16* __restrict__ Bh, const __nv_bfloat16* __restrict__ Bl,
    const float* __restrict__ bias, float* __restrict__ C)
{
    extern __shared__ char smem[];
    const uint32_t tiles = smem_u32(smem);

    const int tid = threadIdx.x;
    const int wid = tid >> 5, lane = tid & 31;
    const int wm = wid >> 2;       // 0..1
    const int wn = wid & 3;        // 0..3
    const int bm = blockIdx.y * 128;
    const int bn = blockIdx.x * 128;

    // load mapping: row = tid>>1 (128 rows), half = (tid&1)*32 bytes
    const int lr = tid >> 1;
    const int lqb = (tid & 1) * 32;   // byte offset in 64B row payload

    float acc[4][4][4];
#pragma unroll
    for (int i = 0; i < 4; i++)
#pragma unroll
        for (int j = 0; j < 4; j++)
#pragma unroll
            for (int k = 0; k < 4; k++) acc[i][j][k] = 0.f;

    auto issue_load = [&](int c) {
        const int seg = c >> 5;
        const int kk = (c & 31) * 32;
        const __nv_bfloat16* ga = ((seg == 2) ? Al : Ah) +
            (size_t)(bm + lr) * DMODEL + kk + lqb / 2;
        const __nv_bfloat16* gb = ((seg == 1) ? Bl : Bh) +
            (size_t)(bn + lr) * DMODEL + kk + lqb / 2;
        const uint32_t st = tiles + (c % NSTG) * STAGE;
        uint32_t sa = st + lr * ROWB + lqb;
        uint32_t sb = st + ASTAGE + lr * ROWB + lqb;
        cp16(sa, ga); cp16(sa + 16, ga + 8);
        cp16(sb, gb); cp16(sb + 16, gb + 8);
    };

    issue_load(0); CP_COMMIT();
    issue_load(1); CP_COMMIT();

    // ldmatrix per-lane address components (precompute)
    const uint32_t a_lrow = (uint32_t)(lane & 15) * ROWB + (uint32_t)(lane >> 4) * 16;
    const uint32_t b_lrow = (uint32_t)((lane >> 4) * 8 + (lane & 7)) * ROWB +
                            (uint32_t)((lane >> 3) & 1) * 16;

    for (int c = 0; c < NCHUNK; c++) {
        CP_WAIT1();
        __syncthreads();
        if (c + 2 < NCHUNK) issue_load(c + 2);
        CP_COMMIT();

        const uint32_t st = tiles + (c % NSTG) * STAGE;
        const uint32_t abase = st + (uint32_t)(wm * 64) * ROWB + a_lrow;
        const uint32_t bbase = st + ASTAGE + (uint32_t)(wn * 32) * ROWB + b_lrow;

#pragma unroll
        for (int ks = 0; ks < 2; ks++) {
            const uint32_t koff = ks * 32;
            uint32_t af[4][4];
#pragma unroll
            for (int mt = 0; mt < 4; mt++)
                LDSM_X4(af[mt][0], af[mt][1], af[mt][2], af[mt][3],
                        abase + (uint32_t)(mt * 16) * ROWB + koff);
            uint32_t bf_[2][4];
#pragma unroll
            for (int np = 0; np < 2; np++)
                LDSM_X4(bf_[np][0], bf_[np][1], bf_[np][2], bf_[np][3],
                        bbase + (uint32_t)(np * 16) * ROWB + koff);
#pragma unroll
            for (int mt = 0; mt < 4; mt++)
#pragma unroll
                for (int nt = 0; nt < 4; nt++) {
                    const uint32_t b0 = bf_[nt >> 1][(nt & 1) * 2];
                    const uint32_t b1 = bf_[nt >> 1][(nt & 1) * 2 + 1];
                    MMA16816(acc[mt][nt], af[mt][0], af[mt][1], af[mt][2], af[mt][3], b0, b1);
                }
        }
    }

    // epilogue
#pragma unroll
    for (int mt = 0; mt < 4; mt++) {
#pragma unroll
        for (int nt = 0; nt < 4; nt++) {
            const int r0 = bm + wm * 64 + mt * 16 + (lane >> 2);
            const int cc = bn + wn * 32 + nt * 8 + (lane & 3) * 2;
            const float b0 = bias[cc], b1 = bias[cc + 1];
            float2 v0, v1;
            v0.x = acc[mt][nt][0] + b0; v0.y = acc[mt][nt][1] + b1;
            v1.x = acc[mt][nt][2] + b0; v1.y = acc[mt][nt][3] + b1;
            *(float2*)&C[(size_t)r0 * DMODEL + cc] = v0;
            *(float2*)&C[(size_t)(r0 + 8) * DMODEL + cc] = v1;
        }
    }
}

// ---------------- banded attention ----------------------------------------
#define QB 8
#define KSPAN (QB - 1 + 2 * HWIN + 1)
#define KST 65

__global__ __launch_bounds__(256) void local_attn_kernel(
    const float* __restrict__ Qg, const float* __restrict__ Kg,
    const float* __restrict__ Vg, float* __restrict__ attn,
    float* __restrict__ ctx)
{
    __shared__ float tile[KSPAN][KST];
    __shared__ float qs[QB][HDIM];
    __shared__ float ps[QB][136];

    const int b = blockIdx.z, h = blockIdx.y;
    const int q0 = blockIdx.x * QB;
    const int tid = threadIdx.x;
    const int warp = tid >> 5, lane = tid & 31;

    const int tbase = q0 - HWIN;
    const int glo = tbase < 0 ? 0 : tbase;
    int ghi = q0 + QB - 1 + HWIN; if (ghi > SEQ - 1) ghi = SEQ - 1;
    const int nrows = ghi - glo + 1;
    const int sh0 = glo - tbase;

    for (int idx = tid; idx < QB * HDIM; idx += 256) {
        int qi = idx >> 6, d = idx & 63;
        qs[qi][d] = Qg[((size_t)(b * SEQ + q0 + qi)) * DMODEL + h * HDIM + d];
    }
    for (int idx = tid; idx < nrows * HDIM; idx += 256) {
        int r = idx >> 6, d = idx & 63;
        tile[sh0 + r][d] = Kg[((size_t)(b * SEQ + glo + r)) * DMODEL + h * HDIM + d];
    }
    __syncthreads();

    const int i = q0 + warp;
    int lo = i - HWIN; if (lo < 0) lo = 0;
    int hi = i + HWIN; if (hi > SEQ - 1) hi = SEQ - 1;
    const int nk = hi - lo + 1;
    const int soff = lo - tbase;

    int roff[5]; bool valid[5];
#pragma unroll
    for (int c = 0; c < 5; c++) {
        int jj = lane + 32 * c;
        valid[c] = (jj < nk);
        int jc = valid[c] ? jj : (nk - 1);
        roff[c] = (soff + jc) * KST;
    }

    const float* tf = &tile[0][0];
    const float* qw = qs[warp];
    float s0 = 0.f, s1 = 0.f, s2 = 0.f, s3 = 0.f, s4 = 0.f;
#pragma unroll 16
    for (int d = 0; d < HDIM; d++) {
        float qd = qw[d];
        s0 += qd * tf[roff[0] + d];
        s1 += qd * tf[roff[1] + d];
        s2 += qd * tf[roff[2] + d];
        s3 += qd * tf[roff[3] + d];
        s4 += qd * tf[roff[4] + d];
    }

    float sc[5] = {s0, s1, s2, s3, s4};
    float mx = -1e30f;
#pragma unroll
    for (int c = 0; c < 5; c++) {
        sc[c] = valid[c] ? sc[c] * 0.125f : -1e30f;
        mx = fmaxf(mx, sc[c]);
    }
#pragma unroll
    for (int o = 16; o; o >>= 1) mx = fmaxf(mx, __shfl_xor_sync(0xffffffffu, mx, o));
    float sum = 0.f;
#pragma unroll
    for (int c = 0; c < 5; c++) {
        sc[c] = valid[c] ? __expf(sc[c] - mx) : 0.f;
        sum += sc[c];
    }
#pragma unroll
    for (int o = 16; o; o >>= 1) sum += __shfl_xor_sync(0xffffffffu, sum, o);
    const float inv = 1.f / sum;

    const size_t arow = ((((size_t)b * NHEAD + h) * SEQ) + i) * SEQ + lo;
#pragma unroll
    for (int c = 0; c < 5; c++) {
        int jj = lane + 32 * c;
        if (jj < nk) {
            float p = sc[c] * inv;
            attn[arow + jj] = p;
            ps[warp][jj] = p;
        }
    }
    __syncthreads();

    for (int idx = tid; idx < nrows * HDIM; idx += 256) {
        int r = idx >> 6, d = idx & 63;
        tile[sh0 + r][d] = Vg[((size_t)(b * SEQ + glo + r)) * DMODEL + h * HDIM + d];
    }
    __syncthreads();

    float a0 = 0.f, a1 = 0.f;
    const int d0 = lane, d1 = lane + 32;
    const float* pw = ps[warp];
    for (int j = 0; j < nk; j++) {
        float p = pw[j];
        a0 += p * tile[soff + j][d0];
        a1 += p * tile[soff + j][d1];
    }
    const size_t cbase = ((size_t)(b * SEQ + i)) * DMODEL + h * HDIM;
    ctx[cbase + d0] = a0;
    ctx[cbase + d1] = a1;
}

// ---------------- launch ---------------------------------------------------
extern "C" void kernel_launch(void* const* d_in, const int* in_sizes, int n_in,
                              void* d_out, int out_size)
{
    const float* x  = (const float*)d_in[0];
    const float* Wq = (const float*)d_in[1];
    const float* bq = (const float*)d_in[2];
    const float* Wk = (const float*)d_in[3];
    const float* bk = (const float*)d_in[4];
    const float* Wv = (const float*)d_in[5];
    const float* bv = (const float*)d_in[6];
    const float* Wo = (const float*)d_in[7];
    const float* bo = (const float*)d_in[8];

    float* out  = (float*)d_out;
    float* attn = out + (size_t)MROWS * DMODEL;

    float *pq, *pk, *pv, *pc;
    cudaGetSymbolAddress((void**)&pq, g_q);
    cudaGetSymbolAddress((void**)&pk, g_k);
    cudaGetSymbolAddress((void**)&pv, g_v);
    cudaGetSymbolAddress((void**)&pc, g_ctx);
    __nv_bfloat16 *xh, *xl, *ch, *cl, *wh, *wl;
    cudaGetSymbolAddress((void**)&xh, g_xh);
    cudaGetSymbolAddress((void**)&xl, g_xl);
    cudaGetSymbolAddress((void**)&ch, g_ch);
    cudaGetSymbolAddress((void**)&cl, g_cl);
    cudaGetSymbolAddress((void**)&wh, g_wh);
    cudaGetSymbolAddress((void**)&wl, g_wl);

    cudaFuncSetAttribute(gemm_tc, cudaFuncAttributeMaxDynamicSharedMemorySize, GEMM_SMEM);

    cudaMemsetAsync(attn, 0,
                    (size_t)BATCH * NHEAD * SEQ * SEQ * sizeof(float), 0);

    const size_t WSZ = (size_t)DMODEL * DMODEL;
    // splits
    split_bf16<<<512, 256>>>(x, xh, xl, MROWS * DMODEL / 4);
    split_bf16<<<256, 256>>>(Wq, wh + 0 * WSZ, wl + 0 * WSZ, (int)(WSZ / 4));
    split_bf16<<<256, 256>>>(Wk, wh + 1 * WSZ, wl + 1 * WSZ, (int)(WSZ / 4));
    split_bf16<<<256, 256>>>(Wv, wh + 2 * WSZ, wl + 2 * WSZ, (int)(WSZ / 4));
    split_bf16<<<256, 256>>>(Wo, wh + 3 * WSZ, wl + 3 * WSZ, (int)(WSZ / 4));

    dim3 gblk(DMODEL / 128, MROWS / 128);   // (8, 32)
    gemm_tc<<<gblk, 256, GEMM_SMEM>>>(xh, xl, wh + 0 * WSZ, wl + 0 * WSZ, bq, pq);
    gemm_tc<<<gblk, 256, GEMM_SMEM>>>(xh, xl, wh + 1 * WSZ, wl + 1 * WSZ, bk, pk);
    gemm_tc<<<gblk, 256, GEMM_SMEM>>>(xh, xl, wh + 2 * WSZ, wl + 2 * WSZ, bv, pv);

    dim3 gattn(SEQ / QB, NHEAD, BATCH);
    local_attn_kernel<<<gattn, 256>>>(pq, pk, pv, attn, pc);

    split_bf16<<<512, 256>>>(pc, ch, cl, MROWS * DMODEL / 4);
    gemm_tc<<<gblk, 256, GEMM_SMEM>>>(ch, cl, wh + 3 * WSZ, wl + 3 * WSZ, bo, out);
}